// round 10
// baseline (speedup 1.0000x reference)
#include <cuda_runtime.h>
#include <cstdint>

// ---------------- fixed problem shape ----------------
#define BB   128
#define NN   8732
#define NNF4 2183        // NN/4 exactly
#define CC   21
#define NCLS 20          // classes 1..20 (background skipped)
#define TOPK 200
#define NMS_T  0.45f
#define CONF_T 0.01f

#define TB1  256         // prep block
#define TB2  256         // per-class block
#define TB3  512         // global block
#define NWORD 7          // ceil(TOPK/32)
#define CANDCAP 1024
#define GTOT (NCLS*TOPK) // 4000
#define GPAD 4096

#define UBASE  0x3C000000u  // bits of 0.0078125 (fallback full-range histogram base)
#define UBASE2 0x3E000000u  // bits of 0.125 (primary pre-gated histogram base)
#define PREGATE 0.125f
#define NBIN  256           // covers both paths (>>18 bin width)

// 0.45f = 0x3EE66666. +/-8 ulps brackets: band ~ +/-9*2^-24 relative,
// strictly wider than (1 ulp div error) + (1 ulp bracket-mul error).
#define T_HI __uint_as_float(0x3EE6666Eu)
#define T_LO __uint_as_float(0x3EE6665Eu)

// ---------------- scratch (device globals; no allocations) ----------------
__device__ float  g_probsT[(size_t)BB * NCLS * NN];   // [b][c-1][i]
__device__ float4 g_boxes [(size_t)BB * NN];          // decoded clamped boxes
__device__ float  g_sc    [(size_t)BB * NCLS * TOPK]; // kept scores (0 if not)
__device__ float4 g_bx    [(size_t)BB * NCLS * TOPK]; // kept boxes

// =====================================================================
// Profiling-slot shims: keep ncu's captured launch on per_class_kernel.
// =====================================================================
__global__ void dummy1_kernel() {}
__global__ void dummy2_kernel() {}

// =====================================================================
// Kernel 1: softmax (class-major output) + box decode. Exact op order.
// =====================================================================
__global__ void __launch_bounds__(TB1)
prep_kernel(const float* __restrict__ loc,
            const float* __restrict__ conf,
            const float* __restrict__ dbox)
{
    int t = blockIdx.x * TB1 + threadIdx.x;
    if (t >= BB * NN) return;
    int b = t / NN;
    int i = t - b * NN;

    const float* cf = conf + (size_t)t * CC;
    float x[CC];
#pragma unroll
    for (int c = 0; c < CC; c++) x[c] = cf[c];
    float m = x[0];
#pragma unroll
    for (int c = 1; c < CC; c++) m = fmaxf(m, x[c]);
    float e[CC];
#pragma unroll
    for (int c = 0; c < CC; c++) e[c] = expf(__fsub_rn(x[c], m));
    float s = 0.0f;
#pragma unroll
    for (int c = 0; c < CC; c++) s = __fadd_rn(s, e[c]);
#pragma unroll
    for (int c = 1; c < CC; c++)
        g_probsT[((size_t)(b * NCLS + (c - 1))) * NN + i] = __fdiv_rn(e[c], s);

    float4 l = ((const float4*)loc)[t];
    float4 d = ((const float4*)dbox)[i];
    float cx = __fadd_rn(d.x, __fmul_rn(__fmul_rn(l.x, 0.1f), d.z));
    float cy = __fadd_rn(d.y, __fmul_rn(__fmul_rn(l.y, 0.1f), d.w));
    float w  = __fmul_rn(d.z, expf(__fmul_rn(l.z, 0.2f)));
    float h  = __fmul_rn(d.w, expf(__fmul_rn(l.w, 0.2f)));
    float x1 = __fsub_rn(cx, __fmul_rn(w, 0.5f));
    float y1 = __fsub_rn(cy, __fmul_rn(h, 0.5f));
    float x2 = __fadd_rn(x1, w);
    float y2 = __fadd_rn(y1, h);
    x1 = fminf(fmaxf(x1, 0.0f), 1.0f);
    y1 = fminf(fmaxf(y1, 0.0f), 1.0f);
    x2 = fminf(fmaxf(x2, 0.0f), 1.0f);
    y2 = fminf(fmaxf(y2, 0.0f), 1.0f);
    g_boxes[t] = make_float4(x1, y1, x2, y2);
}

// =====================================================================
// Kernel 2: per-(batch,class) top-200.
// Threshold via PRE-GATED histogram: atomics only for scores > 0.125
// (~600/block instead of ~7400), register-counted; exact full-range
// fallback if fewer than 200 scores exceed 0.125.
// Then gather + bitonic sort + triangular suppression matrix
// (division-free IoU compare) + serial greedy bit-scan.
// =====================================================================
__global__ void __launch_bounds__(TB2, 6)
per_class_kernel()
{
    __shared__ unsigned s_hist[NBIN];
    __shared__ unsigned long long s_cand[CANDCAP];
    __shared__ float4 s_box[TOPK];
    __shared__ float s_ar[TOPK], s_scv[TOPK];
    __shared__ unsigned s_sup[TOPK * NWORD];
    __shared__ unsigned s_alivew[NWORD];
    __shared__ int s_wcnt[TB2 / 32];
    __shared__ int s_misc[4];        // [0]=cnt125 [1]=threshold bin (-1) [2]=slots

    const int tid  = threadIdx.x;
    const int lane = tid & 31;
    const int wid  = tid >> 5;
    const int blk  = blockIdx.x;          // b*NCLS + c20
    const int b    = blk / NCLS;
    const float4* __restrict__ col4 =
        (const float4*)(g_probsT + (size_t)blk * NN);

    if (tid < 4) s_misc[tid] = (tid == 1) ? -1 : 0;
    for (int i = tid; i < NBIN; i += TB2) s_hist[i] = 0;
    __syncthreads();

    // ---- pass 1: pre-gated histogram (atomics only for s > 0.125)
    //      + register count of scores above the pre-gate ----
    {
        int c125 = 0;
        for (int i4 = tid; i4 < NNF4; i4 += TB2) {
            float4 v = col4[i4];
            float vv[4] = {v.x, v.y, v.z, v.w};
#pragma unroll
            for (int q = 0; q < 4; q++) {
                float s = vv[q];
                if (s > PREGATE) {
                    c125++;
                    atomicAdd(&s_hist[(__float_as_uint(s) - UBASE2) >> 18], 1u);
                }
            }
        }
        c125 = __reduce_add_sync(0xffffffffu, c125);
        if (lane == 0) s_wcnt[wid] = c125;
        __syncthreads();
        if (tid == 0) {
            int t = 0;
            for (int w = 0; w < TB2 / 32; w++) t += s_wcnt[w];
            s_misc[0] = t;
        }
        __syncthreads();
    }
    const bool primary = (s_misc[0] >= TOPK);

    // ---- fallback (rare): full-range histogram over all s > CONF_T ----
    if (!primary) {
        for (int i = tid; i < NBIN; i += TB2) s_hist[i] = 0;
        __syncthreads();
        for (int i4 = tid; i4 < NNF4; i4 += TB2) {
            float4 v = col4[i4];
            float vv[4] = {v.x, v.y, v.z, v.w};
#pragma unroll
            for (int q = 0; q < 4; q++) {
                float s = vv[q];
                if (s > CONF_T)
                    atomicAdd(&s_hist[(__float_as_uint(s) - UBASE) >> 18], 1u);
            }
        }
    }
    __syncthreads();

    // ---- suffix scan of 256 bins (warp 0); crossing at R = TOPK ----
    if (wid == 0) {
        unsigned locs[8];
        unsigned tot = 0;
        int b0 = lane * 8;
#pragma unroll
        for (int j = 7; j >= 0; --j) { tot += s_hist[b0 + j]; locs[j] = tot; }
        unsigned acc = tot;
#pragma unroll
        for (int off = 1; off < 32; off <<= 1) {
            unsigned up = __shfl_down_sync(0xffffffffu, acc, off);
            if (lane + off < 32) acc += up;
        }
        unsigned above_w = acc - tot;    // suffix over lanes > this one
#pragma unroll
        for (int j = 0; j < 8; j++) {
            unsigned suf  = above_w + locs[j];
            unsigned nsuf = (j < 7) ? (above_w + locs[j + 1]) : above_w;
            if (suf >= (unsigned)TOPK && nsuf < (unsigned)TOPK)
                s_misc[1] = b0 + j;
        }
    }
    __syncthreads();
    const int Bbin = s_misc[1];
    const unsigned hbase = primary ? UBASE2 : UBASE;
    const unsigned Ugate = (Bbin >= 0) ? (hbase + ((unsigned)Bbin << 18)) : 0u;

    // ---- pass 2: gather candidates (warp-aggregated slot allocation) ----
    for (int i4 = tid; i4 < NNF4 + (TB2 - NNF4 % TB2); i4 += TB2) {
        float v[4] = {0.f, 0.f, 0.f, 0.f};
        if (i4 < NNF4) {
            float4 t4 = col4[i4];
            v[0] = t4.x; v[1] = t4.y; v[2] = t4.z; v[3] = t4.w;
        }
#pragma unroll
        for (int k = 0; k < 4; k++) {
            float s = v[k];
            bool take = (s > CONF_T) && (__float_as_uint(s) >= Ugate);
            unsigned am = __ballot_sync(0xffffffffu, take);
            if (am) {
                int leader = __ffs(am) - 1;
                int slot0 = 0;
                if (lane == leader) slot0 = atomicAdd(&s_misc[2], __popc(am));
                slot0 = __shfl_sync(0xffffffffu, slot0, leader);
                if (take) {
                    int slot = slot0 + __popc(am & ((1u << lane) - 1u));
                    unsigned idx = (unsigned)(i4 * 4 + k);
                    if (slot < CANDCAP)
                        s_cand[slot] = ((unsigned long long)__float_as_uint(s) << 32)
                                     | (unsigned long long)(0xFFFFFFFFu - idx);
                }
            }
        }
    }
    __syncthreads();
    const int M = min(s_misc[2], CANDCAP);
    int SS = 256;
    while (SS < M) SS <<= 1;
    for (int i = tid; i < SS; i += TB2)
        if (i >= M) s_cand[i] = 0ull;

    // ---- bitonic sort descending over SS keys ----
    for (int size = 2; size <= SS; size <<= 1) {
        for (int stride = size >> 1; stride > 0; stride >>= 1) {
            __syncthreads();
            for (int i = tid; i < SS; i += TB2) {
                int j = i ^ stride;
                if (j > i) {
                    unsigned long long a = s_cand[i], c2 = s_cand[j];
                    bool desc = ((i & size) == 0);
                    if (desc ? (a < c2) : (a > c2)) { s_cand[i] = c2; s_cand[j] = a; }
                }
            }
        }
    }
    __syncthreads();

    // ---- top-K into NMS arrays ----
    const int K = min(M, TOPK);
    for (int k = tid; k < K; k += TB2) {
        unsigned long long key = s_cand[k];
        unsigned idx = 0xFFFFFFFFu - (unsigned)(key & 0xFFFFFFFFull);
        float4 bx = g_boxes[(size_t)b * NN + idx];
        s_box[k] = bx;
        s_ar[k] = __fmul_rn(__fsub_rn(bx.z, bx.x), __fsub_rn(bx.w, bx.y));
        s_scv[k] = __uint_as_float((unsigned)(key >> 32));
    }
    __syncthreads();

    // ---- triangular suppression matrix (division-free compare) ----
    {
        int ntask = K * NWORD;
        for (int t = tid; t < ntask; t += TB2) {
            int i = t / NWORD, w = t - i * NWORD;
            int j0 = w * 32;
            int jlo = max(j0, i + 1), jhi = min(j0 + 32, K);
            unsigned bits = 0u;
            if (jlo < jhi) {
                float4 bi = s_box[i];
                float bar = s_ar[i];
                for (int j = jlo; j < jhi; j++) {
                    float4 bj = s_box[j];
                    float xx1 = fmaxf(bj.x, bi.x), yy1 = fmaxf(bj.y, bi.y);
                    float xx2 = fminf(bj.z, bi.z), yy2 = fminf(bj.w, bi.w);
                    float iw = fmaxf(__fsub_rn(xx2, xx1), 0.0f);
                    float ih = fmaxf(__fsub_rn(yy2, yy1), 0.0f);
                    float inter = __fmul_rn(iw, ih);
                    float den = __fsub_rn(__fadd_rn(s_ar[j], bar), inter);
                    bool sup;
                    if (inter > 0.0f) {
                        // bracket fl(inter/den) vs 0.45 without dividing
                        if (inter > __fmul_rn(den, T_HI))      sup = true;
                        else if (inter < __fmul_rn(den, T_LO)) sup = false;
                        else sup = !(__fdiv_rn(inter, den) <= NMS_T); // rare exact path
                    } else {
                        sup = (den == 0.0f);   // 0/0 -> NaN -> suppress
                    }
                    if (sup) bits |= 1u << (j - j0);
                }
            }
            s_sup[i * NWORD + w] = bits;
        }
    }
    __syncthreads();

    // ---- serial greedy bit-scan (warp 0; alive mask in registers) ----
    if (tid < 32) {
        unsigned aw[NWORD];
#pragma unroll
        for (int w = 0; w < NWORD; w++) {
            int rem = K - w * 32;
            aw[w] = (rem >= 32) ? 0xFFFFFFFFu : ((rem <= 0) ? 0u : ((1u << rem) - 1u));
        }
        int i = 0;
#pragma unroll
        for (int wb = 0; wb < NWORD; wb++) {
            for (int ii = 0; ii < 32 && i < K; ii++, i++) {
                if ((aw[wb] >> ii) & 1u) {
                    const unsigned* row = &s_sup[i * NWORD];
#pragma unroll
                    for (int w = 0; w < NWORD; w++)
                        if (w >= wb) aw[w] &= ~row[w];   // words < wb: rows all-zero
                }
            }
        }
        if (lane == 0) {
#pragma unroll
            for (int w = 0; w < NWORD; w++) s_alivew[w] = aw[w];
        }
    }
    __syncthreads();

    // ---- write kept scores/boxes ----
    for (int k = tid; k < TOPK; k += TB2) {
        bool kp = (k < K) && ((s_alivew[k >> 5] >> (k & 31)) & 1u);
        g_sc[(size_t)blk * TOPK + k] = kp ? s_scv[k] : 0.0f;
        float4 bx = (k < K) ? s_box[k] : make_float4(0.f, 0.f, 0.f, 0.f);
        g_bx[(size_t)blk * TOPK + k] =
            kp ? bx : make_float4(0.f, 0.f, 0.f, 0.f);
    }
}

// =====================================================================
// Kernel 3: per-batch global top-200 (compact nonzeros, dynamic-size sort)
// + per-class stable compaction. One block per batch.
// =====================================================================
__global__ void __launch_bounds__(TB3)
global_kernel(float* __restrict__ out)
{
    __shared__ unsigned long long s_key[GPAD];
    __shared__ float s_gs[TOPK];
    __shared__ int   s_gf[TOPK];
    __shared__ int   s_gc[TOPK];
    __shared__ int   s_gp[TOPK];
    __shared__ int   s_m;

    const int tid = threadIdx.x;
    const int b   = blockIdx.x;
    const float* sb = g_sc + (size_t)b * GTOT;

    if (tid == 0) s_m = 0;
    __syncthreads();

    for (int f = tid; f < GTOT; f += TB3) {
        float s = sb[f];
        if (s > 0.0f) {
            int slot = atomicAdd(&s_m, 1);
            s_key[slot] = ((unsigned long long)__float_as_uint(s) << 32)
                        | (unsigned long long)(0xFFFFFFFFu - (unsigned)f);
        }
    }
    __syncthreads();
    int M = s_m;
    int SS = 256;
    while (SS < M) SS <<= 1;          // <= 4096
    for (int i = tid; i < SS; i += TB3)
        if (i >= M) s_key[i] = 0ull;

    for (int size = 2; size <= SS; size <<= 1) {
        for (int stride = size >> 1; stride > 0; stride >>= 1) {
            __syncthreads();
            for (int i = tid; i < SS; i += TB3) {
                int j = i ^ stride;
                if (j > i) {
                    unsigned long long a = s_key[i], c2 = s_key[j];
                    bool desc = ((i & size) == 0);
                    if (desc ? (a < c2) : (a > c2)) { s_key[i] = c2; s_key[j] = a; }
                }
            }
        }
    }
    __syncthreads();

    if (tid < TOPK) {
        unsigned long long key = s_key[tid];   // SS >= 256 > TOPK
        if (key != 0ull) {
            s_gs[tid] = __uint_as_float((unsigned)(key >> 32));
            int f = (int)(0xFFFFFFFFu - (unsigned)(key & 0xFFFFFFFFull));
            s_gf[tid] = f;
            s_gc[tid] = f / TOPK;
        } else {
            s_gs[tid] = 0.0f; s_gf[tid] = -1; s_gc[tid] = -1;
        }
    }
    __syncthreads();

    if (tid < TOPK && s_gc[tid] >= 0) {
        int c = s_gc[tid], p = 0;
        for (int r = 0; r < tid; r++) p += (s_gc[r] == c) ? 1 : 0;
        s_gp[tid] = p;
    }
    __syncthreads();

    float* ob = out + (size_t)b * CC * TOPK * 5;
    for (int t = tid; t < CC * TOPK * 5; t += TB3) ob[t] = 0.0f;
    __syncthreads();

    if (tid < TOPK && s_gf[tid] >= 0) {
        int f = s_gf[tid];
        int c = s_gc[tid] + 1;                // class label 1..20
        float4 bx = g_bx[(size_t)b * GTOT + f];
        float* row = ob + ((size_t)(c * TOPK + s_gp[tid])) * 5;
        row[0] = s_gs[tid];
        row[1] = bx.x; row[2] = bx.y; row[3] = bx.z; row[4] = bx.w;
    }
}

// =====================================================================
extern "C" void kernel_launch(void* const* d_in, const int* in_sizes, int n_in,
                              void* d_out, int out_size)
{
    const float* loc  = (const float*)d_in[0];
    const float* conf = (const float*)d_in[1];
    const float* dbox = (const float*)d_in[2];
    float* out = (float*)d_out;

    // Profiling-slot shims: keep ncu's captured launch (-s 5 -c 1) on
    // per_class_kernel (confirmed landing there in round 8).
    dummy1_kernel<<<1, 32>>>();
    dummy2_kernel<<<1, 32>>>();

    prep_kernel<<<(BB * NN + TB1 - 1) / TB1, TB1>>>(loc, conf, dbox);
    per_class_kernel<<<BB * NCLS, TB2>>>();
    global_kernel<<<BB, TB3>>>(out);
}

// round 13
// speedup vs baseline: 1.2332x; 1.2332x over previous
#include <cuda_runtime.h>
#include <cstdint>

// ---------------- fixed problem shape ----------------
#define BB   128
#define NN   8732
#define NNF4 2183        // NN/4 exactly
#define CC   21
#define NCLS 20          // classes 1..20 (background skipped)
#define TOPK 200
#define NMS_T  0.45f
#define CONF_T 0.01f

#define TB1  256         // prep block
#define TB2  256         // per-class block
#define TB3  512         // global block
#define NWORD 7          // ceil(TOPK/32)
#define CANDCAP 1024
#define GTOT (NCLS*TOPK) // 4000
#define GPAD 4096

#define UBASE  0x3C000000u  // bits of 0.0078125 (fallback full-range histogram base)
#define UBASE2 0x3E000000u  // bits of 0.125 (primary pre-gated histogram base)
#define PREGATE 0.125f
#define NBIN  256           // covers both paths (>>18 bin width)

// 0.45f = 0x3EE66666. +/-8 ulps brackets: band ~ +/-9*2^-24 relative,
// strictly wider than (1 ulp div error) + (1 ulp bracket-mul error).
#define T_HI __uint_as_float(0x3EE6666Eu)
#define T_LO __uint_as_float(0x3EE6665Eu)

// ---------------- scratch (device globals; no allocations) ----------------
__device__ float  g_probsT[(size_t)BB * NCLS * NN];   // [b][c-1][i]
__device__ float4 g_boxes [(size_t)BB * NN];          // decoded clamped boxes
__device__ float  g_sc    [(size_t)BB * NCLS * TOPK]; // kept scores (0 if not)
__device__ float4 g_bx    [(size_t)BB * NCLS * TOPK]; // kept boxes

// =====================================================================
// Profiling-slot shims: keep ncu's captured launch on per_class_kernel.
// =====================================================================
__global__ void dummy1_kernel() {}
__global__ void dummy2_kernel() {}

// =====================================================================
// Kernel 1: softmax (class-major output) + box decode. Exact op order.
// =====================================================================
__global__ void __launch_bounds__(TB1)
prep_kernel(const float* __restrict__ loc,
            const float* __restrict__ conf,
            const float* __restrict__ dbox)
{
    int t = blockIdx.x * TB1 + threadIdx.x;
    if (t >= BB * NN) return;
    int b = t / NN;
    int i = t - b * NN;

    const float* cf = conf + (size_t)t * CC;
    float x[CC];
#pragma unroll
    for (int c = 0; c < CC; c++) x[c] = cf[c];
    float m = x[0];
#pragma unroll
    for (int c = 1; c < CC; c++) m = fmaxf(m, x[c]);
    float e[CC];
#pragma unroll
    for (int c = 0; c < CC; c++) e[c] = expf(__fsub_rn(x[c], m));
    float s = 0.0f;
#pragma unroll
    for (int c = 0; c < CC; c++) s = __fadd_rn(s, e[c]);
#pragma unroll
    for (int c = 1; c < CC; c++)
        g_probsT[((size_t)(b * NCLS + (c - 1))) * NN + i] = __fdiv_rn(e[c], s);

    float4 l = ((const float4*)loc)[t];
    float4 d = ((const float4*)dbox)[i];
    float cx = __fadd_rn(d.x, __fmul_rn(__fmul_rn(l.x, 0.1f), d.z));
    float cy = __fadd_rn(d.y, __fmul_rn(__fmul_rn(l.y, 0.1f), d.w));
    float w  = __fmul_rn(d.z, expf(__fmul_rn(l.z, 0.2f)));
    float h  = __fmul_rn(d.w, expf(__fmul_rn(l.w, 0.2f)));
    float x1 = __fsub_rn(cx, __fmul_rn(w, 0.5f));
    float y1 = __fsub_rn(cy, __fmul_rn(h, 0.5f));
    float x2 = __fadd_rn(x1, w);
    float y2 = __fadd_rn(y1, h);
    x1 = fminf(fmaxf(x1, 0.0f), 1.0f);
    y1 = fminf(fmaxf(y1, 0.0f), 1.0f);
    x2 = fminf(fmaxf(x2, 0.0f), 1.0f);
    y2 = fminf(fmaxf(y2, 0.0f), 1.0f);
    g_boxes[t] = make_float4(x1, y1, x2, y2);
}

// =====================================================================
// Kernel 2: per-(batch,class) top-200.
// Single fused column pass: pregate hits (>0.125) are histogrammed AND
// staged as keys. Threshold from suffix scan; gather filters the ~600
// staged keys. Exact full-column fallbacks for rare cases.
// NMS: accepted-only parallel sweeps (no O(K^2) matrix, no serial scan),
// with a semantically-inert hard iteration guard (loop provably advances
// by >= 1 per iteration; guard converts any unforeseen hang into a
// bounded exit).
// =====================================================================
__global__ void __launch_bounds__(TB2, 6)
per_class_kernel()
{
    __shared__ unsigned s_hist[NBIN];
    __shared__ unsigned long long s_stage[CANDCAP];
    __shared__ unsigned long long s_cand[CANDCAP];
    __shared__ float4 s_box[TOPK];
    __shared__ float s_ar[TOPK], s_scv[TOPK];
    __shared__ unsigned s_alivew[NWORD];
    __shared__ int s_misc[4];        // [1]=bin(-1) [2]=cand slots [3]=stage count
    __shared__ int s_cur;

    const int tid  = threadIdx.x;
    const int lane = tid & 31;
    const int wid  = tid >> 5;
    const int blk  = blockIdx.x;          // b*NCLS + c20
    const int b    = blk / NCLS;
    const float4* __restrict__ col4 =
        (const float4*)(g_probsT + (size_t)blk * NN);

    if (tid < 4) s_misc[tid] = (tid == 1) ? -1 : 0;
    for (int i = tid; i < NBIN; i += TB2) s_hist[i] = 0;
    __syncthreads();

    // ---- pass 1 (fused): histogram + stage keys for scores > 0.125 ----
    for (int i4 = tid; i4 < NNF4 + (TB2 - NNF4 % TB2); i4 += TB2) {
        float v[4] = {0.f, 0.f, 0.f, 0.f};
        if (i4 < NNF4) {
            float4 t4 = col4[i4];
            v[0] = t4.x; v[1] = t4.y; v[2] = t4.z; v[3] = t4.w;
        }
#pragma unroll
        for (int k = 0; k < 4; k++) {
            float s = v[k];
            bool hit = (s > PREGATE);
            unsigned am = __ballot_sync(0xffffffffu, hit);
            if (am) {
                int leader = __ffs(am) - 1;
                int slot0 = 0;
                if (lane == leader) slot0 = atomicAdd(&s_misc[3], __popc(am));
                slot0 = __shfl_sync(0xffffffffu, slot0, leader);
                if (hit) {
                    unsigned u = __float_as_uint(s);
                    atomicAdd(&s_hist[(u - UBASE2) >> 18], 1u);
                    int slot = slot0 + __popc(am & ((1u << lane) - 1u));
                    unsigned idx = (unsigned)(i4 * 4 + k);
                    if (slot < CANDCAP)
                        s_stage[slot] = ((unsigned long long)u << 32)
                                      | (unsigned long long)(0xFFFFFFFFu - idx);
                }
            }
        }
    }
    __syncthreads();
    const int cnt125 = s_misc[3];
    const bool primary = (cnt125 >= TOPK);
    const bool stageOK = (cnt125 <= CANDCAP);

    // ---- fallback (rare): full-range histogram over all s > CONF_T ----
    if (!primary) {
        for (int i = tid; i < NBIN; i += TB2) s_hist[i] = 0;
        __syncthreads();
        for (int i4 = tid; i4 < NNF4; i4 += TB2) {
            float4 v = col4[i4];
            float vv[4] = {v.x, v.y, v.z, v.w};
#pragma unroll
            for (int q = 0; q < 4; q++) {
                float s = vv[q];
                if (s > CONF_T)
                    atomicAdd(&s_hist[(__float_as_uint(s) - UBASE) >> 18], 1u);
            }
        }
        __syncthreads();
    }

    // ---- suffix scan of 256 bins (warp 0); crossing at R = TOPK ----
    if (wid == 0) {
        unsigned locs[8];
        unsigned tot = 0;
        int b0 = lane * 8;
#pragma unroll
        for (int j = 7; j >= 0; --j) { tot += s_hist[b0 + j]; locs[j] = tot; }
        unsigned acc = tot;
#pragma unroll
        for (int off = 1; off < 32; off <<= 1) {
            unsigned up = __shfl_down_sync(0xffffffffu, acc, off);
            if (lane + off < 32) acc += up;
        }
        unsigned above_w = acc - tot;    // suffix over lanes > this one
#pragma unroll
        for (int j = 0; j < 8; j++) {
            unsigned suf  = above_w + locs[j];
            unsigned nsuf = (j < 7) ? (above_w + locs[j + 1]) : above_w;
            if (suf >= (unsigned)TOPK && nsuf < (unsigned)TOPK)
                s_misc[1] = b0 + j;
        }
    }
    __syncthreads();
    const int Bbin = s_misc[1];
    const unsigned hbase = primary ? UBASE2 : UBASE;
    const unsigned Ugate = (Bbin >= 0) ? (hbase + ((unsigned)Bbin << 18)) : 0u;

    // ---- gather candidates ----
    if (primary && stageOK) {
        // filter the staged keys (~600) instead of rescanning the column
        int nb = ((cnt125 + TB2 - 1) / TB2) * TB2;
        for (int t = tid; t < nb; t += TB2) {
            unsigned long long key = 0ull;
            bool take = false;
            if (t < cnt125) {
                key = s_stage[t];
                take = ((unsigned)(key >> 32) >= Ugate);
            }
            unsigned am = __ballot_sync(0xffffffffu, take);
            if (am) {
                int leader = __ffs(am) - 1;
                int slot0 = 0;
                if (lane == leader) slot0 = atomicAdd(&s_misc[2], __popc(am));
                slot0 = __shfl_sync(0xffffffffu, slot0, leader);
                if (take) {
                    int slot = slot0 + __popc(am & ((1u << lane) - 1u));
                    if (slot < CANDCAP) s_cand[slot] = key;
                }
            }
        }
    } else {
        // full-column gather (stage overflow or fallback threshold)
        for (int i4 = tid; i4 < NNF4 + (TB2 - NNF4 % TB2); i4 += TB2) {
            float v[4] = {0.f, 0.f, 0.f, 0.f};
            if (i4 < NNF4) {
                float4 t4 = col4[i4];
                v[0] = t4.x; v[1] = t4.y; v[2] = t4.z; v[3] = t4.w;
            }
#pragma unroll
            for (int k = 0; k < 4; k++) {
                float s = v[k];
                bool take = (s > CONF_T) && (__float_as_uint(s) >= Ugate);
                unsigned am = __ballot_sync(0xffffffffu, take);
                if (am) {
                    int leader = __ffs(am) - 1;
                    int slot0 = 0;
                    if (lane == leader) slot0 = atomicAdd(&s_misc[2], __popc(am));
                    slot0 = __shfl_sync(0xffffffffu, slot0, leader);
                    if (take) {
                        int slot = slot0 + __popc(am & ((1u << lane) - 1u));
                        unsigned idx = (unsigned)(i4 * 4 + k);
                        if (slot < CANDCAP)
                            s_cand[slot] = ((unsigned long long)__float_as_uint(s) << 32)
                                         | (unsigned long long)(0xFFFFFFFFu - idx);
                    }
                }
            }
        }
    }
    __syncthreads();
    const int M = min(s_misc[2], CANDCAP);
    int SS = 256;
    while (SS < M) SS <<= 1;
    for (int i = tid; i < SS; i += TB2)
        if (i >= M) s_cand[i] = 0ull;

    // ---- bitonic sort descending over SS keys ----
    for (int size = 2; size <= SS; size <<= 1) {
        for (int stride = size >> 1; stride > 0; stride >>= 1) {
            __syncthreads();
            for (int i = tid; i < SS; i += TB2) {
                int j = i ^ stride;
                if (j > i) {
                    unsigned long long a = s_cand[i], c2 = s_cand[j];
                    bool desc = ((i & size) == 0);
                    if (desc ? (a < c2) : (a > c2)) { s_cand[i] = c2; s_cand[j] = a; }
                }
            }
        }
    }
    __syncthreads();

    // ---- top-K into NMS arrays + init alive words ----
    const int K = min(M, TOPK);
    for (int k = tid; k < K; k += TB2) {
        unsigned long long key = s_cand[k];
        unsigned idx = 0xFFFFFFFFu - (unsigned)(key & 0xFFFFFFFFull);
        float4 bx = g_boxes[(size_t)b * NN + idx];
        s_box[k] = bx;
        s_ar[k] = __fmul_rn(__fsub_rn(bx.z, bx.x), __fsub_rn(bx.w, bx.y));
        s_scv[k] = __uint_as_float((unsigned)(key >> 32));
    }
    if (tid < NWORD) {
        int rem = K - tid * 32;
        s_alivew[tid] = (rem >= 32) ? 0xFFFFFFFFu
                                    : ((rem <= 0) ? 0u : ((1u << rem) - 1u));
    }
    if (tid == 0) s_cur = 0;
    __syncthreads();

    // ---- greedy NMS: one parallel sweep per ACCEPTED box ----
    {
        int i = (K > 0) ? 0 : K;
        // Hard guard: loop advances i by >= 1 each iteration, so it runs at
        // most K (<= TOPK) times; the guard is semantically inert and only
        // bounds execution against unforeseen states.
        for (int iter = 0; i < K && iter < TOPK; ++iter) {
            float4 bi = s_box[i];
            float bar = s_ar[i];
            // K - i - 1 <= 199 < TB2: at most one j per thread
            int j = i + 1 + tid;
            if (j < K && ((s_alivew[j >> 5] >> (j & 31)) & 1u)) {
                float4 bj = s_box[j];
                float xx1 = fmaxf(bj.x, bi.x), yy1 = fmaxf(bj.y, bi.y);
                float xx2 = fminf(bj.z, bi.z), yy2 = fminf(bj.w, bi.w);
                float iw = fmaxf(__fsub_rn(xx2, xx1), 0.0f);
                float ih = fmaxf(__fsub_rn(yy2, yy1), 0.0f);
                float inter = __fmul_rn(iw, ih);
                float den = __fsub_rn(__fadd_rn(s_ar[j], bar), inter);
                bool sup;
                if (inter > 0.0f) {
                    if (inter > __fmul_rn(den, T_HI))      sup = true;
                    else if (inter < __fmul_rn(den, T_LO)) sup = false;
                    else sup = !(__fdiv_rn(inter, den) <= NMS_T); // rare exact path
                } else {
                    sup = (den == 0.0f);   // 0/0 -> NaN -> suppress
                }
                if (sup) atomicAnd(&s_alivew[j >> 5], ~(1u << (j & 31)));
            }
            __syncthreads();
            if (tid == 0) {
                int ni = K;
                int w = (i + 1) >> 5;
                if (w < NWORD) {
                    unsigned mask = s_alivew[w] & (0xFFFFFFFFu << ((i + 1) & 31));
                    while (true) {
                        if (mask) { ni = (w << 5) + __ffs(mask) - 1; break; }
                        if (++w >= NWORD) break;
                        mask = s_alivew[w];
                    }
                }
                s_cur = ni;
            }
            __syncthreads();
            i = s_cur;
        }
    }

    // ---- write kept scores/boxes ----
    for (int k = tid; k < TOPK; k += TB2) {
        bool kp = (k < K) && ((s_alivew[k >> 5] >> (k & 31)) & 1u);
        g_sc[(size_t)blk * TOPK + k] = kp ? s_scv[k] : 0.0f;
        float4 bx = (k < K) ? s_box[k] : make_float4(0.f, 0.f, 0.f, 0.f);
        g_bx[(size_t)blk * TOPK + k] =
            kp ? bx : make_float4(0.f, 0.f, 0.f, 0.f);
    }
}

// =====================================================================
// Kernel 3: per-batch global top-200 (compact nonzeros, dynamic-size sort)
// + per-class stable compaction. One block per batch.
// =====================================================================
__global__ void __launch_bounds__(TB3)
global_kernel(float* __restrict__ out)
{
    __shared__ unsigned long long s_key[GPAD];
    __shared__ float s_gs[TOPK];
    __shared__ int   s_gf[TOPK];
    __shared__ int   s_gc[TOPK];
    __shared__ int   s_gp[TOPK];
    __shared__ int   s_m;

    const int tid = threadIdx.x;
    const int b   = blockIdx.x;
    const float* sb = g_sc + (size_t)b * GTOT;

    if (tid == 0) s_m = 0;
    __syncthreads();

    for (int f = tid; f < GTOT; f += TB3) {
        float s = sb[f];
        if (s > 0.0f) {
            int slot = atomicAdd(&s_m, 1);
            s_key[slot] = ((unsigned long long)__float_as_uint(s) << 32)
                        | (unsigned long long)(0xFFFFFFFFu - (unsigned)f);
        }
    }
    __syncthreads();
    int M = s_m;
    int SS = 256;
    while (SS < M) SS <<= 1;          // <= 4096
    for (int i = tid; i < SS; i += TB3)
        if (i >= M) s_key[i] = 0ull;

    for (int size = 2; size <= SS; size <<= 1) {
        for (int stride = size >> 1; stride > 0; stride >>= 1) {
            __syncthreads();
            for (int i = tid; i < SS; i += TB3) {
                int j = i ^ stride;
                if (j > i) {
                    unsigned long long a = s_key[i], c2 = s_key[j];
                    bool desc = ((i & size) == 0);
                    if (desc ? (a < c2) : (a > c2)) { s_key[i] = c2; s_key[j] = a; }
                }
            }
        }
    }
    __syncthreads();

    if (tid < TOPK) {
        unsigned long long key = s_key[tid];   // SS >= 256 > TOPK
        if (key != 0ull) {
            s_gs[tid] = __uint_as_float((unsigned)(key >> 32));
            int f = (int)(0xFFFFFFFFu - (unsigned)(key & 0xFFFFFFFFull));
            s_gf[tid] = f;
            s_gc[tid] = f / TOPK;
        } else {
            s_gs[tid] = 0.0f; s_gf[tid] = -1; s_gc[tid] = -1;
        }
    }
    __syncthreads();

    if (tid < TOPK && s_gc[tid] >= 0) {
        int c = s_gc[tid], p = 0;
        for (int r = 0; r < tid; r++) p += (s_gc[r] == c) ? 1 : 0;
        s_gp[tid] = p;
    }
    __syncthreads();

    float* ob = out + (size_t)b * CC * TOPK * 5;
    for (int t = tid; t < CC * TOPK * 5; t += TB3) ob[t] = 0.0f;
    __syncthreads();

    if (tid < TOPK && s_gf[tid] >= 0) {
        int f = s_gf[tid];
        int c = s_gc[tid] + 1;                // class label 1..20
        float4 bx = g_bx[(size_t)b * GTOT + f];
        float* row = ob + ((size_t)(c * TOPK + s_gp[tid])) * 5;
        row[0] = s_gs[tid];
        row[1] = bx.x; row[2] = bx.y; row[3] = bx.z; row[4] = bx.w;
    }
}

// =====================================================================
extern "C" void kernel_launch(void* const* d_in, const int* in_sizes, int n_in,
                              void* d_out, int out_size)
{
    const float* loc  = (const float*)d_in[0];
    const float* conf = (const float*)d_in[1];
    const float* dbox = (const float*)d_in[2];
    float* out = (float*)d_out;

    // Profiling-slot shims: keep ncu's captured launch (-s 5 -c 1) on
    // per_class_kernel (confirmed landing there in rounds 8/10).
    dummy1_kernel<<<1, 32>>>();
    dummy2_kernel<<<1, 32>>>();

    prep_kernel<<<(BB * NN + TB1 - 1) / TB1, TB1>>>(loc, conf, dbox);
    per_class_kernel<<<BB * NCLS, TB2>>>();
    global_kernel<<<BB, TB3>>>(out);
}